// round 3
// baseline (speedup 1.0000x reference)
#include <cuda_runtime.h>

#define BB 2
#define SS 2048
#define EE 1024
#define HH 16
#define DD 64

typedef unsigned long long u64;

__device__ __forceinline__ u64 fma2(u64 a, u64 b, u64 c) {
    u64 d; asm("fma.rn.f32x2 %0, %1, %2, %3;" : "=l"(d) : "l"(a), "l"(b), "l"(c)); return d;
}
__device__ __forceinline__ u64 mul2(u64 a, u64 b) {
    u64 d; asm("mul.rn.f32x2 %0, %1, %2;" : "=l"(d) : "l"(a), "l"(b)); return d;
}
__device__ __forceinline__ u64 add2(u64 a, u64 b) {
    u64 d; asm("add.rn.f32x2 %0, %1, %2;" : "=l"(d) : "l"(a), "l"(b)); return d;
}
__device__ __forceinline__ u64 pack2(float lo, float hi) {
    u64 d; asm("mov.b64 %0, {%1, %2};" : "=l"(d) : "f"(lo), "f"(hi)); return d;
}
__device__ __forceinline__ void unpack2(u64 v, float& lo, float& hi) {
    asm("mov.b64 {%0, %1}, %2;" : "=f"(lo), "=f"(hi) : "l"(v));
}

// ---------------- scratch ----------------
__device__ float g_q[BB*HH*SS*DD];     // [b,h,s,d]
__device__ float g_k[BB*HH*SS*DD];
__device__ float g_v[BB*HH*SS*DD];
__device__ float g_attn[BB*SS*EE];     // [b,s,h*d]

// ---------------- QKV projection: [65536 x 64] @ Wt[64 x 64] x3 ----------------
// Block: 64 rows x 192 cols (3 mats x 64). Thread: 4 rows x 4 cols x 3 mats.
__global__ __launch_bounds__(256) void qkv_kernel(
    const float* __restrict__ x,
    const float* __restrict__ Wq, const float* __restrict__ Bq,
    const float* __restrict__ Wk, const float* __restrict__ Bk,
    const float* __restrict__ Wv, const float* __restrict__ Bv)
{
    __shared__ float As[16][64];       // 4KB
    __shared__ u64 Bs2[3][16][64];     // 24KB, duplicated pairs

    int tid = threadIdx.x;
    int r0  = blockIdx.x * 64;
    int tx  = tid & 15;                // c4 = tx*4
    int ty  = tid >> 4;                // m  = ty*4

    u64 acc[3][2][4];
    #pragma unroll
    for (int m_ = 0; m_ < 3; ++m_)
        #pragma unroll
        for (int p = 0; p < 2; ++p)
            #pragma unroll
            for (int n = 0; n < 4; ++n) acc[m_][p][n] = 0ull;

    int lr = tid >> 2;                 // 0..63
    int lk = (tid & 3) * 4;            // 0,4,8,12
    const float* Ws[3] = {Wq, Wk, Wv};

    for (int k0 = 0; k0 < 64; k0 += 16) {
        float4 xv = *(const float4*)(x + (size_t)(r0 + lr) * 64 + k0 + lk);
        As[lk+0][lr] = xv.x; As[lk+1][lr] = xv.y; As[lk+2][lr] = xv.z; As[lk+3][lr] = xv.w;
        #pragma unroll
        for (int m_ = 0; m_ < 3; ++m_) {
            float4 wv = *(const float4*)(Ws[m_] + (size_t)lr * 64 + k0 + lk);
            Bs2[m_][lk+0][lr] = pack2(wv.x, wv.x);
            Bs2[m_][lk+1][lr] = pack2(wv.y, wv.y);
            Bs2[m_][lk+2][lr] = pack2(wv.z, wv.z);
            Bs2[m_][lk+3][lr] = pack2(wv.w, wv.w);
        }
        __syncthreads();

        #pragma unroll
        for (int kk = 0; kk < 16; ++kk) {
            ulonglong2 av = *(ulonglong2*)&As[kk][ty*4];
            u64 ap[2] = {av.x, av.y};
            #pragma unroll
            for (int m_ = 0; m_ < 3; ++m_) {
                ulonglong2 b01 = *(ulonglong2*)&Bs2[m_][kk][tx*4];
                ulonglong2 b23 = *(ulonglong2*)&Bs2[m_][kk][tx*4+2];
                u64 bq[4] = {b01.x, b01.y, b23.x, b23.y};
                #pragma unroll
                for (int p = 0; p < 2; ++p)
                    #pragma unroll
                    for (int n = 0; n < 4; ++n)
                        acc[m_][p][n] = fma2(ap[p], bq[n], acc[m_][p][n]);
            }
        }
        __syncthreads();
    }

    const float* Bias[3] = {Bq, Bk, Bv};
    float* Gs[3];
    Gs[0] = g_q; Gs[1] = g_k; Gs[2] = g_v;
    #pragma unroll
    for (int m_ = 0; m_ < 3; ++m_) {
        float4 bv4 = *(const float4*)(Bias[m_] + tx*4);
        float bb[4] = {bv4.x, bv4.y, bv4.z, bv4.w};
        #pragma unroll
        for (int p = 0; p < 2; ++p) {
            float lo[4], hi[4];
            #pragma unroll
            for (int n = 0; n < 4; ++n) unpack2(acc[m_][p][n], lo[n], hi[n]);
            #pragma unroll
            for (int lane = 0; lane < 2; ++lane) {
                int r = r0 + ty*4 + p*2 + lane;
                int h = r & 15, bs = r >> 4, s = bs & 2047, b = bs >> 11;
                float* op = Gs[m_] + ((size_t)((b*HH + h)*SS) + s)*DD + tx*4;
                float* src = lane ? hi : lo;
                float4 t;
                t.x = src[0] + bb[0]; t.y = src[1] + bb[1];
                t.z = src[2] + bb[2]; t.w = src[3] + bb[3];
                *(float4*)op = t;
            }
        }
    }
}

// ---------------- flash attention, packed f32x2, one thread per query row ----------------
__global__ __launch_bounds__(128) void attn_kernel()
{
    __shared__ float4 ks4[1024];    // 64 keys x 64 dims
    __shared__ float4 vs4[1024];

    int bh   = blockIdx.y;
    int tid  = threadIdx.x;
    int bx   = 15 - blockIdx.x;                    // heavy blocks launch first
    int qrow = bx * 128 + tid;

    const ulonglong2* qp = (const ulonglong2*)(g_q + ((size_t)bh*SS + qrow)*DD);
    u64 scale2 = pack2(0.125f, 0.125f);
    u64 qr2[32];
    #pragma unroll
    for (int d4 = 0; d4 < 16; ++d4) {
        ulonglong2 t = qp[d4];
        qr2[2*d4]   = mul2(t.x, scale2);
        qr2[2*d4+1] = mul2(t.y, scale2);
    }
    u64 o2[32];
    #pragma unroll
    for (int i = 0; i < 32; ++i) o2[i] = 0ull;
    float m = -3.0e38f, l = 0.f;

    int ntiles = bx * 2 + 2;
    const float4* kb = (const float4*)(g_k + (size_t)bh*SS*DD);
    const float4* vb = (const float4*)(g_v + (size_t)bh*SS*DD);

    for (int t = 0; t < ntiles; ++t) {
        int k0 = t * 64;
        #pragma unroll
        for (int u = 0; u < 8; ++u) {
            int idx = tid + 128*u;
            ks4[idx] = kb[k0*16 + idx];
            vs4[idx] = vb[k0*16 + idx];
        }
        __syncthreads();

        for (int ch = 0; ch < 4; ++ch) {
            int j0 = k0 + ch*16;
            if (j0 > qrow) continue;
            const ulonglong2* kc = (const ulonglong2*)ks4 + ch*256;
            const ulonglong2* vc = (const ulonglong2*)vs4 + ch*256;

            float s[16];
            float tmax = -3.0e38f;
            #pragma unroll
            for (int j = 0; j < 16; ++j) {
                u64 a0 = 0ull, a1 = 0ull;
                #pragma unroll
                for (int d4 = 0; d4 < 16; ++d4) {
                    ulonglong2 kk = kc[j*16 + d4];
                    a0 = fma2(qr2[2*d4],   kk.x, a0);
                    a1 = fma2(qr2[2*d4+1], kk.y, a1);
                }
                a0 = add2(a0, a1);
                float lo, hi; unpack2(a0, lo, hi);
                float acc = lo + hi;
                acc = (j0 + j <= qrow) ? acc : -3.0e38f;
                s[j] = acc;
                tmax = fmaxf(tmax, acc);
            }
            float newm = fmaxf(m, tmax);
            float corr = __expf(m - newm);
            m = newm;
            l *= corr;
            u64 corr2 = pack2(corr, corr);
            #pragma unroll
            for (int i = 0; i < 32; ++i) o2[i] = mul2(o2[i], corr2);
            #pragma unroll
            for (int j = 0; j < 16; ++j) {
                float p = __expf(s[j] - newm);
                l += p;
                u64 p2 = pack2(p, p);
                #pragma unroll
                for (int d4 = 0; d4 < 16; ++d4) {
                    ulonglong2 vv = vc[j*16 + d4];
                    o2[2*d4]   = fma2(p2, vv.x, o2[2*d4]);
                    o2[2*d4+1] = fma2(p2, vv.y, o2[2*d4+1]);
                }
            }
        }
        __syncthreads();
    }

    float inv = 1.f / l;
    u64 inv2 = pack2(inv, inv);
    int b = bh >> 4, h = bh & (HH-1);
    ulonglong2* op = (ulonglong2*)(g_attn + ((size_t)(b*SS + qrow))*EE + h*DD);
    #pragma unroll
    for (int d4 = 0; d4 < 16; ++d4) {
        ulonglong2 t;
        t.x = mul2(o2[2*d4],   inv2);
        t.y = mul2(o2[2*d4+1], inv2);
        op[d4] = t;
    }
}

// ---------------- output projection: [4096,1024] @ W^T + b, FFMA2 ----------------
// Block: 128x128 tile. Thread: 8 rows x 8 cols (4 m-pairs).
__global__ __launch_bounds__(256) void proj_kernel(
    const float* __restrict__ W, const float* __restrict__ bias, float* __restrict__ out)
{
    __shared__ float As[16][128];   // 8KB
    __shared__ u64  Bs2[16][128];   // 16KB, duplicated pairs

    int tid = threadIdx.x;
    int m0 = blockIdx.y * 128;
    int n0 = blockIdx.x * 128;
    int tx = tid & 15;              // n = n0 + tx*8
    int ty = tid >> 4;              // m = m0 + ty*8

    u64 acc2[4][8];
    #pragma unroll
    for (int p = 0; p < 4; ++p)
        #pragma unroll
        for (int n = 0; n < 8; ++n) acc2[p][n] = 0ull;

    int lr = tid >> 1;              // 0..127
    int lk = (tid & 1) * 8;         // 0 or 8

    for (int k0 = 0; k0 < EE; k0 += 16) {
        float4 a0 = *(const float4*)(g_attn + (size_t)(m0+lr)*EE + k0 + lk);
        float4 a1 = *(const float4*)(g_attn + (size_t)(m0+lr)*EE + k0 + lk + 4);
        As[lk+0][lr] = a0.x; As[lk+1][lr] = a0.y; As[lk+2][lr] = a0.z; As[lk+3][lr] = a0.w;
        As[lk+4][lr] = a1.x; As[lk+5][lr] = a1.y; As[lk+6][lr] = a1.z; As[lk+7][lr] = a1.w;
        float4 b0 = *(const float4*)(W + (size_t)(n0+lr)*EE + k0 + lk);
        float4 b1 = *(const float4*)(W + (size_t)(n0+lr)*EE + k0 + lk + 4);
        Bs2[lk+0][lr] = pack2(b0.x, b0.x); Bs2[lk+1][lr] = pack2(b0.y, b0.y);
        Bs2[lk+2][lr] = pack2(b0.z, b0.z); Bs2[lk+3][lr] = pack2(b0.w, b0.w);
        Bs2[lk+4][lr] = pack2(b1.x, b1.x); Bs2[lk+5][lr] = pack2(b1.y, b1.y);
        Bs2[lk+6][lr] = pack2(b1.z, b1.z); Bs2[lk+7][lr] = pack2(b1.w, b1.w);
        __syncthreads();

        #pragma unroll
        for (int kk = 0; kk < 16; ++kk) {
            ulonglong2 aA = *(ulonglong2*)&As[kk][ty*8];
            ulonglong2 aB = *(ulonglong2*)&As[kk][ty*8+4];
            u64 ap[4] = {aA.x, aA.y, aB.x, aB.y};
            ulonglong2 q0 = *(ulonglong2*)&Bs2[kk][tx*8];
            ulonglong2 q1 = *(ulonglong2*)&Bs2[kk][tx*8+2];
            ulonglong2 q2 = *(ulonglong2*)&Bs2[kk][tx*8+4];
            ulonglong2 q3 = *(ulonglong2*)&Bs2[kk][tx*8+6];
            u64 bq[8] = {q0.x, q0.y, q1.x, q1.y, q2.x, q2.y, q3.x, q3.y};
            #pragma unroll
            for (int p = 0; p < 4; ++p)
                #pragma unroll
                for (int n = 0; n < 8; ++n)
                    acc2[p][n] = fma2(ap[p], bq[n], acc2[p][n]);
        }
        __syncthreads();
    }

    float4 bl = *(const float4*)(bias + n0 + tx*8);
    float4 bh_ = *(const float4*)(bias + n0 + tx*8 + 4);
    float bb[8] = {bl.x, bl.y, bl.z, bl.w, bh_.x, bh_.y, bh_.z, bh_.w};
    #pragma unroll
    for (int p = 0; p < 4; ++p) {
        float lo[8], hi[8];
        #pragma unroll
        for (int n = 0; n < 8; ++n) unpack2(acc2[p][n], lo[n], hi[n]);
        #pragma unroll
        for (int lane = 0; lane < 2; ++lane) {
            int mrow = m0 + ty*8 + p*2 + lane;
            float* src = lane ? hi : lo;
            float4 t0, t1;
            t0.x = src[0]+bb[0]; t0.y = src[1]+bb[1]; t0.z = src[2]+bb[2]; t0.w = src[3]+bb[3];
            t1.x = src[4]+bb[4]; t1.y = src[5]+bb[5]; t1.z = src[6]+bb[6]; t1.w = src[7]+bb[7];
            *(float4*)(out + (size_t)mrow*EE + n0 + tx*8)     = t0;
            *(float4*)(out + (size_t)mrow*EE + n0 + tx*8 + 4) = t1;
        }
    }
}

// ---------------- launch ----------------
extern "C" void kernel_launch(void* const* d_in, const int* in_sizes, int n_in,
                              void* d_out, int out_size) {
    const float* x  = (const float*)d_in[0];
    const float* Wq = (const float*)d_in[1];
    const float* Bq = (const float*)d_in[2];
    const float* Wk = (const float*)d_in[3];
    const float* Bk = (const float*)d_in[4];
    const float* Wv = (const float*)d_in[5];
    const float* Bv = (const float*)d_in[6];
    const float* Pw = (const float*)d_in[7];
    const float* Pb = (const float*)d_in[8];
    float* out = (float*)d_out;

    qkv_kernel<<<1024, 256>>>(x, Wq, Bq, Wk, Bk, Wv, Bv);
    attn_kernel<<<dim3(16, 32), 128>>>();
    proj_kernel<<<dim3(8, 32), 256>>>(Pw, Pb, out);
}

// round 4
// speedup vs baseline: 2.7015x; 2.7015x over previous
#include <cuda_runtime.h>

#define BB 2
#define SS 2048
#define EE 1024
#define HH 16
#define DD 64

typedef unsigned long long u64;
typedef unsigned int u32;

__device__ __forceinline__ u64 pack2(float lo, float hi) {
    u64 d; asm("mov.b64 %0, {%1, %2};" : "=l"(d) : "f"(lo), "f"(hi)); return d;
}
__device__ __forceinline__ void unpack2(u64 v, float& lo, float& hi) {
    asm("mov.b64 {%0, %1}, %2;" : "=f"(lo), "=f"(hi) : "l"(v));
}
__device__ __forceinline__ u64 fma2(u64 a, u64 b, u64 c) {
    u64 d; asm("fma.rn.f32x2 %0, %1, %2, %3;" : "=l"(d) : "l"(a), "l"(b), "l"(c)); return d;
}
__device__ __forceinline__ u32 cvt_tf32(float f) {
    u32 u; asm("cvt.rna.tf32.f32 %0, %1;" : "=r"(u) : "f"(f)); return u;
}
__device__ __forceinline__ void mma_tf32(float* c, const u32* a, u32 b0, u32 b1) {
    asm("mma.sync.aligned.m16n8k8.row.col.f32.tf32.tf32.f32 "
        "{%0,%1,%2,%3}, {%4,%5,%6,%7}, {%8,%9}, {%0,%1,%2,%3};"
        : "+f"(c[0]), "+f"(c[1]), "+f"(c[2]), "+f"(c[3])
        : "r"(a[0]), "r"(a[1]), "r"(a[2]), "r"(a[3]), "r"(b0), "r"(b1));
}

// ---------------- scratch ----------------
__device__ float g_q[BB*HH*SS*DD];     // [b,h,s,d]
__device__ float g_k[BB*HH*SS*DD];
__device__ float g_v[BB*HH*SS*DD];
__device__ float g_attn[BB*SS*EE];     // [b,s,h*d]

// ---------------- QKV projection (R3 version, profiled 130us) ----------------
__global__ __launch_bounds__(256) void qkv_kernel(
    const float* __restrict__ x,
    const float* __restrict__ Wq, const float* __restrict__ Bq,
    const float* __restrict__ Wk, const float* __restrict__ Bk,
    const float* __restrict__ Wv, const float* __restrict__ Bv)
{
    __shared__ float As[16][64];
    __shared__ u64 Bs2[3][16][64];

    int tid = threadIdx.x;
    int r0  = blockIdx.x * 64;
    int tx  = tid & 15;
    int ty  = tid >> 4;

    u64 acc[3][2][4];
    #pragma unroll
    for (int m_ = 0; m_ < 3; ++m_)
        #pragma unroll
        for (int p = 0; p < 2; ++p)
            #pragma unroll
            for (int n = 0; n < 4; ++n) acc[m_][p][n] = 0ull;

    int lr = tid >> 2;
    int lk = (tid & 3) * 4;
    const float* Ws[3] = {Wq, Wk, Wv};

    for (int k0 = 0; k0 < 64; k0 += 16) {
        float4 xv = *(const float4*)(x + (size_t)(r0 + lr) * 64 + k0 + lk);
        As[lk+0][lr] = xv.x; As[lk+1][lr] = xv.y; As[lk+2][lr] = xv.z; As[lk+3][lr] = xv.w;
        #pragma unroll
        for (int m_ = 0; m_ < 3; ++m_) {
            float4 wv = *(const float4*)(Ws[m_] + (size_t)lr * 64 + k0 + lk);
            Bs2[m_][lk+0][lr] = pack2(wv.x, wv.x);
            Bs2[m_][lk+1][lr] = pack2(wv.y, wv.y);
            Bs2[m_][lk+2][lr] = pack2(wv.z, wv.z);
            Bs2[m_][lk+3][lr] = pack2(wv.w, wv.w);
        }
        __syncthreads();

        #pragma unroll
        for (int kk = 0; kk < 16; ++kk) {
            ulonglong2 av = *(ulonglong2*)&As[kk][ty*4];
            u64 ap[2] = {av.x, av.y};
            #pragma unroll
            for (int m_ = 0; m_ < 3; ++m_) {
                ulonglong2 b01 = *(ulonglong2*)&Bs2[m_][kk][tx*4];
                ulonglong2 b23 = *(ulonglong2*)&Bs2[m_][kk][tx*4+2];
                u64 bq[4] = {b01.x, b01.y, b23.x, b23.y};
                #pragma unroll
                for (int p = 0; p < 2; ++p)
                    #pragma unroll
                    for (int n = 0; n < 4; ++n)
                        acc[m_][p][n] = fma2(ap[p], bq[n], acc[m_][p][n]);
            }
        }
        __syncthreads();
    }

    const float* Bias[3] = {Bq, Bk, Bv};
    float* Gs[3];
    Gs[0] = g_q; Gs[1] = g_k; Gs[2] = g_v;
    #pragma unroll
    for (int m_ = 0; m_ < 3; ++m_) {
        float4 bv4 = *(const float4*)(Bias[m_] + tx*4);
        float bb[4] = {bv4.x, bv4.y, bv4.z, bv4.w};
        #pragma unroll
        for (int p = 0; p < 2; ++p) {
            float lo[4], hi[4];
            #pragma unroll
            for (int n = 0; n < 4; ++n) unpack2(acc[m_][p][n], lo[n], hi[n]);
            #pragma unroll
            for (int lane = 0; lane < 2; ++lane) {
                int r = r0 + ty*4 + p*2 + lane;
                int h = r & 15, bs = r >> 4, s = bs & 2047, b = bs >> 11;
                float* op = Gs[m_] + ((size_t)((b*HH + h)*SS) + s)*DD + tx*4;
                float* src = lane ? hi : lo;
                float4 t;
                t.x = src[0] + bb[0]; t.y = src[1] + bb[1];
                t.z = src[2] + bb[2]; t.w = src[3] + bb[3];
                *(float4*)op = t;
            }
        }
    }
}

// ---------------- flash attention via tf32 mma.sync ----------------
// Block: 64 query rows, 4 warps (16 rows each). Key tiles of 64.
// Kt[key][d] stride 68 (tf32), Vt[key][d] stride 68 (tf32).
// P (per-warp 16x64, stride 68) aliases Kt after a block-wide sync.
#define KSTR 68
__global__ __launch_bounds__(128) void attn_kernel()
{
    __shared__ u32 smem_buf[2*64*KSTR];   // 34816 B
    u32* Kt = smem_buf;
    u32* Vt = smem_buf + 64*KSTR;

    int tid  = threadIdx.x;
    int warp = tid >> 5;
    int lane = tid & 31;
    int g    = lane >> 2;         // 0..7
    int tg   = lane & 3;          // 0..3

    int bh = blockIdx.y;
    int qt = 31 - (int)blockIdx.x;        // heavy tiles first
    int q0 = qt * 64;

    const float* Qb = g_q + (size_t)bh*SS*DD;
    const float* Kb = g_k + (size_t)bh*SS*DD;
    const float* Vb = g_v + (size_t)bh*SS*DD;

    int r0 = q0 + warp*16 + g;            // global query rows for this thread
    int r1 = r0 + 8;

    // Q fragments (scaled by 1/8, tf32)
    u32 qa[8][4];
    #pragma unroll
    for (int k = 0; k < 8; ++k) {
        qa[k][0] = cvt_tf32(Qb[(size_t)r0*64 + k*8 + tg]     * 0.125f);
        qa[k][1] = cvt_tf32(Qb[(size_t)r1*64 + k*8 + tg]     * 0.125f);
        qa[k][2] = cvt_tf32(Qb[(size_t)r0*64 + k*8 + tg + 4] * 0.125f);
        qa[k][3] = cvt_tf32(Qb[(size_t)r1*64 + k*8 + tg + 4] * 0.125f);
    }

    float accO[8][4];
    #pragma unroll
    for (int n = 0; n < 8; ++n)
        #pragma unroll
        for (int j = 0; j < 4; ++j) accO[n][j] = 0.f;
    float m0 = -3.0e38f, m1 = -3.0e38f, l0 = 0.f, l1 = 0.f;

    for (int t = 0; t <= qt; ++t) {
        int k0 = t * 64;
        __syncthreads();                  // P/K region reusable, V consumed
        // cooperative load K,V tiles (fp32 -> tf32)
        #pragma unroll
        for (int u = 0; u < 8; ++u) {
            int lin = u*128 + tid;
            int key = lin >> 4;
            int d4  = (lin & 15) * 4;
            float4 kv = *(const float4*)(Kb + (size_t)(k0+key)*64 + d4);
            float4 vv = *(const float4*)(Vb + (size_t)(k0+key)*64 + d4);
            uint4 ku, vu;
            ku.x = cvt_tf32(kv.x); ku.y = cvt_tf32(kv.y); ku.z = cvt_tf32(kv.z); ku.w = cvt_tf32(kv.w);
            vu.x = cvt_tf32(vv.x); vu.y = cvt_tf32(vv.y); vu.z = cvt_tf32(vv.z); vu.w = cvt_tf32(vv.w);
            *(uint4*)&Kt[key*KSTR + d4] = ku;
            *(uint4*)&Vt[key*KSTR + d4] = vu;
        }
        __syncthreads();

        // S = Q K^T  (16 x 64 per warp)
        float sfr[8][4];
        #pragma unroll
        for (int n = 0; n < 8; ++n) {
            float c[4] = {0.f, 0.f, 0.f, 0.f};
            #pragma unroll
            for (int k = 0; k < 8; ++k) {
                u32 b0 = Kt[(n*8 + g)*KSTR + k*8 + tg];
                u32 b1 = Kt[(n*8 + g)*KSTR + k*8 + tg + 4];
                mma_tf32(c, qa[k], b0, b1);
            }
            sfr[n][0] = c[0]; sfr[n][1] = c[1]; sfr[n][2] = c[2]; sfr[n][3] = c[3];
        }

        // causal mask (diagonal tile only)
        if (t == qt) {
            #pragma unroll
            for (int n = 0; n < 8; ++n) {
                int col = k0 + n*8 + 2*tg;
                if (col     > r0) sfr[n][0] = -1e30f;
                if (col + 1 > r0) sfr[n][1] = -1e30f;
                if (col     > r1) sfr[n][2] = -1e30f;
                if (col + 1 > r1) sfr[n][3] = -1e30f;
            }
        }

        // online softmax
        float mx0 = -3.0e38f, mx1 = -3.0e38f;
        #pragma unroll
        for (int n = 0; n < 8; ++n) {
            mx0 = fmaxf(mx0, fmaxf(sfr[n][0], sfr[n][1]));
            mx1 = fmaxf(mx1, fmaxf(sfr[n][2], sfr[n][3]));
        }
        mx0 = fmaxf(mx0, __shfl_xor_sync(0xffffffffu, mx0, 1));
        mx0 = fmaxf(mx0, __shfl_xor_sync(0xffffffffu, mx0, 2));
        mx1 = fmaxf(mx1, __shfl_xor_sync(0xffffffffu, mx1, 1));
        mx1 = fmaxf(mx1, __shfl_xor_sync(0xffffffffu, mx1, 2));
        float nm0 = fmaxf(m0, mx0), nm1 = fmaxf(m1, mx1);
        float cr0 = __expf(m0 - nm0), cr1 = __expf(m1 - nm1);
        m0 = nm0; m1 = nm1;
        l0 *= cr0; l1 *= cr1;
        #pragma unroll
        for (int n = 0; n < 8; ++n) {
            accO[n][0] *= cr0; accO[n][1] *= cr0;
            accO[n][2] *= cr1; accO[n][3] *= cr1;
        }
        float p[8][4];
        float ps0 = 0.f, ps1 = 0.f;
        #pragma unroll
        for (int n = 0; n < 8; ++n) {
            p[n][0] = __expf(sfr[n][0] - nm0);
            p[n][1] = __expf(sfr[n][1] - nm0);
            p[n][2] = __expf(sfr[n][2] - nm1);
            p[n][3] = __expf(sfr[n][3] - nm1);
            ps0 += p[n][0] + p[n][1];
            ps1 += p[n][2] + p[n][3];
        }
        l0 += ps0; l1 += ps1;

        // store P (tf32) into per-warp region aliasing Kt
        __syncthreads();                  // all warps done reading Kt
        u32* Pw = Kt + warp*16*KSTR;
        #pragma unroll
        for (int n = 0; n < 8; ++n) {
            Pw[g*KSTR       + n*8 + 2*tg]     = cvt_tf32(p[n][0]);
            Pw[g*KSTR       + n*8 + 2*tg + 1] = cvt_tf32(p[n][1]);
            Pw[(g+8)*KSTR   + n*8 + 2*tg]     = cvt_tf32(p[n][2]);
            Pw[(g+8)*KSTR   + n*8 + 2*tg + 1] = cvt_tf32(p[n][3]);
        }
        __syncwarp();

        // O += P V   (16 x 64 per warp)
        #pragma unroll
        for (int k2 = 0; k2 < 8; ++k2) {
            u32 a[4];
            a[0] = Pw[g*KSTR     + k2*8 + tg];
            a[1] = Pw[(g+8)*KSTR + k2*8 + tg];
            a[2] = Pw[g*KSTR     + k2*8 + tg + 4];
            a[3] = Pw[(g+8)*KSTR + k2*8 + tg + 4];
            #pragma unroll
            for (int n2 = 0; n2 < 8; ++n2) {
                u32 b0 = Vt[(k2*8 + tg)*KSTR     + n2*8 + g];
                u32 b1 = Vt[(k2*8 + tg + 4)*KSTR + n2*8 + g];
                mma_tf32(accO[n2], a, b0, b1);
            }
        }
    }

    // finalize l across the 4-lane groups
    l0 += __shfl_xor_sync(0xffffffffu, l0, 1);
    l0 += __shfl_xor_sync(0xffffffffu, l0, 2);
    l1 += __shfl_xor_sync(0xffffffffu, l1, 1);
    l1 += __shfl_xor_sync(0xffffffffu, l1, 2);
    float inv0 = 1.f / l0, inv1 = 1.f / l1;

    int b = bh >> 4, h = bh & (HH-1);
    float* out0 = g_attn + ((size_t)(b*SS + r0))*EE + h*DD;
    float* out1 = g_attn + ((size_t)(b*SS + r1))*EE + h*DD;
    #pragma unroll
    for (int n2 = 0; n2 < 8; ++n2) {
        float2 v0, v1;
        v0.x = accO[n2][0]*inv0; v0.y = accO[n2][1]*inv0;
        v1.x = accO[n2][2]*inv1; v1.y = accO[n2][3]*inv1;
        *(float2*)(out0 + n2*8 + 2*tg) = v0;
        *(float2*)(out1 + n2*8 + 2*tg) = v1;
    }
}

// ---------------- output projection (R2 version, known good) ----------------
__global__ __launch_bounds__(256) void proj_kernel(
    const float* __restrict__ W, const float* __restrict__ bias, float* __restrict__ out)
{
    __shared__ float As[16][128];
    __shared__ float Bs[16][64];

    int tid = threadIdx.x;
    int m0 = blockIdx.y * 128;
    int n0 = blockIdx.x * 64;
    int tx = tid & 15;
    int ty = tid >> 4;

    float acc[8][4];
    #pragma unroll
    for (int i = 0; i < 8; ++i)
        #pragma unroll
        for (int j = 0; j < 4; ++j) acc[i][j] = 0.f;

    int lmA = tid >> 1;
    int lkA = (tid & 1) * 8;
    int lmB = tid >> 2;
    int lkB = (tid & 3) * 4;

    for (int k0 = 0; k0 < EE; k0 += 16) {
        float4 a0 = *(const float4*)(g_attn + (size_t)(m0+lmA)*EE + k0 + lkA);
        float4 a1 = *(const float4*)(g_attn + (size_t)(m0+lmA)*EE + k0 + lkA + 4);
        float4 b0 = *(const float4*)(W + (size_t)(n0+lmB)*EE + k0 + lkB);
        As[lkA+0][lmA] = a0.x; As[lkA+1][lmA] = a0.y; As[lkA+2][lmA] = a0.z; As[lkA+3][lmA] = a0.w;
        As[lkA+4][lmA] = a1.x; As[lkA+5][lmA] = a1.y; As[lkA+6][lmA] = a1.z; As[lkA+7][lmA] = a1.w;
        Bs[lkB+0][lmB] = b0.x; Bs[lkB+1][lmB] = b0.y; Bs[lkB+2][lmB] = b0.z; Bs[lkB+3][lmB] = b0.w;
        __syncthreads();

        #pragma unroll
        for (int kk = 0; kk < 16; ++kk) {
            float4 av0 = *(float4*)&As[kk][ty*8];
            float4 av1 = *(float4*)&As[kk][ty*8+4];
            float4 bv  = *(float4*)&Bs[kk][tx*4];
            float am[8] = {av0.x, av0.y, av0.z, av0.w, av1.x, av1.y, av1.z, av1.w};
            float bn[4] = {bv.x, bv.y, bv.z, bv.w};
            #pragma unroll
            for (int i = 0; i < 8; ++i)
                #pragma unroll
                for (int j = 0; j < 4; ++j)
                    acc[i][j] += am[i]*bn[j];
        }
        __syncthreads();
    }

    float4 bvec = *(const float4*)(bias + n0 + tx*4);
    #pragma unroll
    for (int i = 0; i < 8; ++i) {
        float4 t;
        t.x = acc[i][0] + bvec.x;
        t.y = acc[i][1] + bvec.y;
        t.z = acc[i][2] + bvec.z;
        t.w = acc[i][3] + bvec.w;
        *(float4*)(out + (size_t)(m0 + ty*8 + i)*EE + n0 + tx*4) = t;
    }
}

// ---------------- launch ----------------
extern "C" void kernel_launch(void* const* d_in, const int* in_sizes, int n_in,
                              void* d_out, int out_size) {
    const float* x  = (const float*)d_in[0];
    const float* Wq = (const float*)d_in[1];
    const float* Bq = (const float*)d_in[2];
    const float* Wk = (const float*)d_in[3];
    const float* Bk = (const float*)d_in[4];
    const float* Wv = (const float*)d_in[5];
    const float* Bv = (const float*)d_in[6];
    const float* Pw = (const float*)d_in[7];
    const float* Pb = (const float*)d_in[8];
    float* out = (float*)d_out;

    qkv_kernel<<<1024, 256>>>(x, Wq, Bq, Wk, Bk, Wv, Bv);
    attn_kernel<<<dim3(32, 32), 128>>>();
    proj_kernel<<<dim3(16, 32), 256>>>(Pw, Pb, out);
}

// round 7
// speedup vs baseline: 2.8363x; 1.0499x over previous
#include <cuda_runtime.h>

#define BB 2
#define SS 2048
#define EE 1024
#define HH 16
#define DD 64

typedef unsigned long long u64;
typedef unsigned int u32;

__device__ __forceinline__ u32 cvt_tf32(float f) {
    u32 u; asm("cvt.rna.tf32.f32 %0, %1;" : "=r"(u) : "f"(f)); return u;
}
__device__ __forceinline__ void mma_tf32(float* c, const u32* a, u32 b0, u32 b1) {
    asm("mma.sync.aligned.m16n8k8.row.col.f32.tf32.tf32.f32 "
        "{%0,%1,%2,%3}, {%4,%5,%6,%7}, {%8,%9}, {%0,%1,%2,%3};"
        : "+f"(c[0]), "+f"(c[1]), "+f"(c[2]), "+f"(c[3])
        : "r"(a[0]), "r"(a[1]), "r"(a[2]), "r"(a[3]), "r"(b0), "r"(b1));
}

// ---------------- scratch ----------------
__device__ float g_q[BB*HH*SS*DD];     // [b,h,s,d]
__device__ float g_k[BB*HH*SS*DD];
__device__ float g_v[BB*HH*SS*DD];
__device__ float g_attn[BB*SS*EE];     // [b,s,h*d]

// ---------------- QKV projection via tf32 mma, x split hi+lo ----------------
// GEMM: x[65536 x 64] @ W^T (3 mats of 64) -> N=192. Block: 64 rows x 192 cols.
// 8 warps as 2(m) x 4(n): warp tile 32 x 48.
#define QSTR 36
__global__ __launch_bounds__(256) void qkv_kernel(
    const float* __restrict__ x,
    const float* __restrict__ Wq, const float* __restrict__ Bq,
    const float* __restrict__ Wk, const float* __restrict__ Bk,
    const float* __restrict__ Wv, const float* __restrict__ Bv)
{
    __shared__ u32 Ah[64*QSTR];     // x hi, [row][k], stride 36
    __shared__ u32 Al[64*QSTR];     // x lo
    __shared__ u32 Wsm[192*QSTR];   // W (q|k|v), [n][k]

    int tid  = threadIdx.x;
    int warp = tid >> 5;
    int lane = tid & 31;
    int g    = lane >> 2;
    int tg   = lane & 3;
    int wm0  = (warp >> 2) * 32;    // 0 or 32
    int wn0  = (warp & 3) * 48;     // 0,48,96,144
    int r0   = blockIdx.x * 64;

    const float* Ws[3] = {Wq, Wk, Wv};

    float acc[2][6][4];
    #pragma unroll
    for (int mf = 0; mf < 2; ++mf)
        #pragma unroll
        for (int nf = 0; nf < 6; ++nf)
            #pragma unroll
            for (int j = 0; j < 4; ++j) acc[mf][nf][j] = 0.f;

    for (int k0 = 0; k0 < 64; k0 += 32) {
        if (k0) __syncthreads();
        // fill x (hi/lo): 64 rows x 32 cols
        #pragma unroll
        for (int it = 0; it < 2; ++it) {
            int idx = it*256 + tid;
            int row = idx >> 3;
            int c4  = (idx & 7) * 4;
            float4 v = *(const float4*)(x + (size_t)(r0+row)*64 + k0 + c4);
            uint4 h, l;
            h.x = cvt_tf32(v.x); l.x = cvt_tf32(v.x - __uint_as_float(h.x));
            h.y = cvt_tf32(v.y); l.y = cvt_tf32(v.y - __uint_as_float(h.y));
            h.z = cvt_tf32(v.z); l.z = cvt_tf32(v.z - __uint_as_float(h.z));
            h.w = cvt_tf32(v.w); l.w = cvt_tf32(v.w - __uint_as_float(h.w));
            *(uint4*)&Ah[row*QSTR + c4] = h;
            *(uint4*)&Al[row*QSTR + c4] = l;
        }
        // fill W: 192 rows x 32 cols
        #pragma unroll
        for (int it = 0; it < 6; ++it) {
            int idx = it*256 + tid;
            int row = idx >> 3;
            int c4  = (idx & 7) * 4;
            float4 v = *(const float4*)(Ws[row >> 6] + (size_t)(row & 63)*64 + k0 + c4);
            uint4 h;
            h.x = cvt_tf32(v.x); h.y = cvt_tf32(v.y);
            h.z = cvt_tf32(v.z); h.w = cvt_tf32(v.w);
            *(uint4*)&Wsm[row*QSTR + c4] = h;
        }
        __syncthreads();

        #pragma unroll
        for (int ks = 0; ks < 4; ++ks) {
            int kk = ks * 8;
            u32 ah[2][4], al[2][4];
            #pragma unroll
            for (int mf = 0; mf < 2; ++mf) {
                int mr = wm0 + mf*16;
                ah[mf][0] = Ah[(mr+g)*QSTR   + kk + tg];
                ah[mf][1] = Ah[(mr+g+8)*QSTR + kk + tg];
                ah[mf][2] = Ah[(mr+g)*QSTR   + kk + tg + 4];
                ah[mf][3] = Ah[(mr+g+8)*QSTR + kk + tg + 4];
                al[mf][0] = Al[(mr+g)*QSTR   + kk + tg];
                al[mf][1] = Al[(mr+g+8)*QSTR + kk + tg];
                al[mf][2] = Al[(mr+g)*QSTR   + kk + tg + 4];
                al[mf][3] = Al[(mr+g+8)*QSTR + kk + tg + 4];
            }
            #pragma unroll
            for (int nf = 0; nf < 6; ++nf) {
                u32 b0 = Wsm[(wn0 + nf*8 + g)*QSTR + kk + tg];
                u32 b1 = Wsm[(wn0 + nf*8 + g)*QSTR + kk + tg + 4];
                #pragma unroll
                for (int mf = 0; mf < 2; ++mf) {
                    mma_tf32(acc[mf][nf], ah[mf], b0, b1);
                    mma_tf32(acc[mf][nf], al[mf], b0, b1);
                }
            }
        }
    }

    // epilogue: bias + scatter to [b,h,s,d]
    const float* Bias[3] = {Bq, Bk, Bv};
    float* Gs[3];
    Gs[0] = g_q; Gs[1] = g_k; Gs[2] = g_v;
    #pragma unroll
    for (int mf = 0; mf < 2; ++mf) {
        int ra = r0 + wm0 + mf*16 + g;
        int rb = ra + 8;
        #pragma unroll
        for (int nf = 0; nf < 6; ++nf) {
            int gc  = wn0 + nf*8 + 2*tg;
            int mat = gc >> 6;
            int c   = gc & 63;
            float b0 = Bias[mat][c], b1 = Bias[mat][c+1];
            {
                int h = ra & 15, bs = ra >> 4, s = bs & 2047, b = bs >> 11;
                float2 t; t.x = acc[mf][nf][0] + b0; t.y = acc[mf][nf][1] + b1;
                *(float2*)(Gs[mat] + ((size_t)((b*HH + h)*SS) + s)*DD + c) = t;
            }
            {
                int h = rb & 15, bs = rb >> 4, s = bs & 2047, b = bs >> 11;
                float2 t; t.x = acc[mf][nf][2] + b0; t.y = acc[mf][nf][3] + b1;
                *(float2*)(Gs[mat] + ((size_t)((b*HH + h)*SS) + s)*DD + c) = t;
            }
        }
    }
}

// ---------------- flash attention via tf32 mma.sync (R4, validated) ----------------
#define KSTR 68
__global__ __launch_bounds__(128) void attn_kernel()
{
    __shared__ u32 smem_buf[2*64*KSTR];   // 34816 B
    u32* Kt = smem_buf;
    u32* Vt = smem_buf + 64*KSTR;

    int tid  = threadIdx.x;
    int warp = tid >> 5;
    int lane = tid & 31;
    int g    = lane >> 2;
    int tg   = lane & 3;

    int bh = blockIdx.y;
    int qt = 31 - (int)blockIdx.x;
    int q0 = qt * 64;

    const float* Qb = g_q + (size_t)bh*SS*DD;
    const float* Kb = g_k + (size_t)bh*SS*DD;
    const float* Vb = g_v + (size_t)bh*SS*DD;

    int r0 = q0 + warp*16 + g;
    int r1 = r0 + 8;

    u32 qa[8][4];
    #pragma unroll
    for (int k = 0; k < 8; ++k) {
        qa[k][0] = cvt_tf32(Qb[(size_t)r0*64 + k*8 + tg]     * 0.125f);
        qa[k][1] = cvt_tf32(Qb[(size_t)r1*64 + k*8 + tg]     * 0.125f);
        qa[k][2] = cvt_tf32(Qb[(size_t)r0*64 + k*8 + tg + 4] * 0.125f);
        qa[k][3] = cvt_tf32(Qb[(size_t)r1*64 + k*8 + tg + 4] * 0.125f);
    }

    float accO[8][4];
    #pragma unroll
    for (int n = 0; n < 8; ++n)
        #pragma unroll
        for (int j = 0; j < 4; ++j) accO[n][j] = 0.f;
    float m0 = -3.0e38f, m1 = -3.0e38f, l0 = 0.f, l1 = 0.f;

    for (int t = 0; t <= qt; ++t) {
        int k0 = t * 64;
        __syncthreads();
        #pragma unroll
        for (int u = 0; u < 8; ++u) {
            int lin = u*128 + tid;
            int key = lin >> 4;
            int d4  = (lin & 15) * 4;
            float4 kv = *(const float4*)(Kb + (size_t)(k0+key)*64 + d4);
            float4 vv = *(const float4*)(Vb + (size_t)(k0+key)*64 + d4);
            uint4 ku, vu;
            ku.x = cvt_tf32(kv.x); ku.y = cvt_tf32(kv.y); ku.z = cvt_tf32(kv.z); ku.w = cvt_tf32(kv.w);
            vu.x = cvt_tf32(vv.x); vu.y = cvt_tf32(vv.y); vu.z = cvt_tf32(vv.z); vu.w = cvt_tf32(vv.w);
            *(uint4*)&Kt[key*KSTR + d4] = ku;
            *(uint4*)&Vt[key*KSTR + d4] = vu;
        }
        __syncthreads();

        float sfr[8][4];
        #pragma unroll
        for (int n = 0; n < 8; ++n) {
            float c[4] = {0.f, 0.f, 0.f, 0.f};
            #pragma unroll
            for (int k = 0; k < 8; ++k) {
                u32 b0 = Kt[(n*8 + g)*KSTR + k*8 + tg];
                u32 b1 = Kt[(n*8 + g)*KSTR + k*8 + tg + 4];
                mma_tf32(c, qa[k], b0, b1);
            }
            sfr[n][0] = c[0]; sfr[n][1] = c[1]; sfr[n][2] = c[2]; sfr[n][3] = c[3];
        }

        if (t == qt) {
            #pragma unroll
            for (int n = 0; n < 8; ++n) {
                int col = k0 + n*8 + 2*tg;
                if (col     > r0) sfr[n][0] = -1e30f;
                if (col + 1 > r0) sfr[n][1] = -1e30f;
                if (col     > r1) sfr[n][2] = -1e30f;
                if (col + 1 > r1) sfr[n][3] = -1e30f;
            }
        }

        float mx0 = -3.0e38f, mx1 = -3.0e38f;
        #pragma unroll
        for (int n = 0; n < 8; ++n) {
            mx0 = fmaxf(mx0, fmaxf(sfr[n][0], sfr[n][1]));
            mx1 = fmaxf(mx1, fmaxf(sfr[n][2], sfr[n][3]));
        }
        mx0 = fmaxf(mx0, __shfl_xor_sync(0xffffffffu, mx0, 1));
        mx0 = fmaxf(mx0, __shfl_xor_sync(0xffffffffu, mx0, 2));
        mx1 = fmaxf(mx1, __shfl_xor_sync(0xffffffffu, mx1, 1));
        mx1 = fmaxf(mx1, __shfl_xor_sync(0xffffffffu, mx1, 2));
        float nm0 = fmaxf(m0, mx0), nm1 = fmaxf(m1, mx1);
        float cr0 = __expf(m0 - nm0), cr1 = __expf(m1 - nm1);
        m0 = nm0; m1 = nm1;
        l0 *= cr0; l1 *= cr1;
        #pragma unroll
        for (int n = 0; n < 8; ++n) {
            accO[n][0] *= cr0; accO[n][1] *= cr0;
            accO[n][2] *= cr1; accO[n][3] *= cr1;
        }
        float p[8][4];
        float ps0 = 0.f, ps1 = 0.f;
        #pragma unroll
        for (int n = 0; n < 8; ++n) {
            p[n][0] = __expf(sfr[n][0] - nm0);
            p[n][1] = __expf(sfr[n][1] - nm0);
            p[n][2] = __expf(sfr[n][2] - nm1);
            p[n][3] = __expf(sfr[n][3] - nm1);
            ps0 += p[n][0] + p[n][1];
            ps1 += p[n][2] + p[n][3];
        }
        l0 += ps0; l1 += ps1;

        __syncthreads();
        u32* Pw = Kt + warp*16*KSTR;
        #pragma unroll
        for (int n = 0; n < 8; ++n) {
            Pw[g*KSTR       + n*8 + 2*tg]     = cvt_tf32(p[n][0]);
            Pw[g*KSTR       + n*8 + 2*tg + 1] = cvt_tf32(p[n][1]);
            Pw[(g+8)*KSTR   + n*8 + 2*tg]     = cvt_tf32(p[n][2]);
            Pw[(g+8)*KSTR   + n*8 + 2*tg + 1] = cvt_tf32(p[n][3]);
        }
        __syncwarp();

        #pragma unroll
        for (int k2 = 0; k2 < 8; ++k2) {
            u32 a[4];
            a[0] = Pw[g*KSTR     + k2*8 + tg];
            a[1] = Pw[(g+8)*KSTR + k2*8 + tg];
            a[2] = Pw[g*KSTR     + k2*8 + tg + 4];
            a[3] = Pw[(g+8)*KSTR + k2*8 + tg + 4];
            #pragma unroll
            for (int n2 = 0; n2 < 8; ++n2) {
                u32 b0 = Vt[(k2*8 + tg)*KSTR     + n2*8 + g];
                u32 b1 = Vt[(k2*8 + tg + 4)*KSTR + n2*8 + g];
                mma_tf32(accO[n2], a, b0, b1);
            }
        }
    }

    l0 += __shfl_xor_sync(0xffffffffu, l0, 1);
    l0 += __shfl_xor_sync(0xffffffffu, l0, 2);
    l1 += __shfl_xor_sync(0xffffffffu, l1, 1);
    l1 += __shfl_xor_sync(0xffffffffu, l1, 2);
    float inv0 = 1.f / l0, inv1 = 1.f / l1;

    int b = bh >> 4, h = bh & (HH-1);
    float* out0 = g_attn + ((size_t)(b*SS + r0))*EE + h*DD;
    float* out1 = g_attn + ((size_t)(b*SS + r1))*EE + h*DD;
    #pragma unroll
    for (int n2 = 0; n2 < 8; ++n2) {
        float2 v0, v1;
        v0.x = accO[n2][0]*inv0; v0.y = accO[n2][1]*inv0;
        v1.x = accO[n2][2]*inv1; v1.y = accO[n2][3]*inv1;
        *(float2*)(out0 + n2*8 + 2*tg) = v0;
        *(float2*)(out1 + n2*8 + 2*tg) = v1;
    }
}

// ---------------- output projection via tf32 mma ----------------
// [4096 x 1024] @ W^T[1024 x 1024]. Block 128x128, warps 4(m) x 2(n), warp 32x64.
#define PSTR 20
__global__ __launch_bounds__(256) void proj_kernel(
    const float* __restrict__ W, const float* __restrict__ bias, float* __restrict__ out)
{
    __shared__ u32 As[128*PSTR];   // [m][k] stride 20
    __shared__ u32 Bs[128*PSTR];   // [n][k] stride 20

    int tid  = threadIdx.x;
    int warp = tid >> 5;
    int lane = tid & 31;
    int g    = lane >> 2;
    int tg   = lane & 3;
    int wm0  = (warp >> 1) * 32;   // 0,32,64,96
    int wn0  = (warp & 1) * 64;    // 0,64
    int m0   = blockIdx.y * 128;
    int n0   = blockIdx.x * 128;

    float acc[2][8][4];
    #pragma unroll
    for (int mf = 0; mf < 2; ++mf)
        #pragma unroll
        for (int nf = 0; nf < 8; ++nf)
            #pragma unroll
            for (int j = 0; j < 4; ++j) acc[mf][nf][j] = 0.f;

    for (int k0 = 0; k0 < EE; k0 += 16) {
        if (k0) __syncthreads();
        #pragma unroll
        for (int it = 0; it < 2; ++it) {
            int idx = it*256 + tid;
            int row = idx >> 2;
            int c4  = (idx & 3) * 4;
            float4 a = *(const float4*)(g_attn + (size_t)(m0+row)*EE + k0 + c4);
            uint4 ha;
            ha.x = cvt_tf32(a.x); ha.y = cvt_tf32(a.y); ha.z = cvt_tf32(a.z); ha.w = cvt_tf32(a.w);
            *(uint4*)&As[row*PSTR + c4] = ha;
            float4 b = *(const float4*)(W + (size_t)(n0+row)*EE + k0 + c4);
            uint4 hb;
            hb.x = cvt_tf32(b.x); hb.y = cvt_tf32(b.y); hb.z = cvt_tf32(b.z); hb.w = cvt_tf32(b.w);
            *(uint4*)&Bs[row*PSTR + c4] = hb;
        }
        __syncthreads();

        #pragma unroll
        for (int ks = 0; ks < 2; ++ks) {
            int kk = ks * 8;
            u32 a[2][4];
            #pragma unroll
            for (int mf = 0; mf < 2; ++mf) {
                int mr = wm0 + mf*16;
                a[mf][0] = As[(mr+g)*PSTR   + kk + tg];
                a[mf][1] = As[(mr+g+8)*PSTR + kk + tg];
                a[mf][2] = As[(mr+g)*PSTR   + kk + tg + 4];
                a[mf][3] = As[(mr+g+8)*PSTR + kk + tg + 4];
            }
            #pragma unroll
            for (int nf = 0; nf < 8; ++nf) {
                u32 b0 = Bs[(wn0 + nf*8 + g)*PSTR + kk + tg];
                u32 b1 = Bs[(wn0 + nf*8 + g)*PSTR + kk + tg + 4];
                #pragma unroll
                for (int mf = 0; mf < 2; ++mf)
                    mma_tf32(acc[mf][nf], a[mf], b0, b1);
            }
        }
    }

    #pragma unroll
    for (int mf = 0; mf < 2; ++mf) {
        int ra = m0 + wm0 + mf*16 + g;
        int rb = ra + 8;
        #pragma unroll
        for (int nf = 0; nf < 8; ++nf) {
            int gc = n0 + wn0 + nf*8 + 2*tg;
            float b0 = bias[gc], b1 = bias[gc+1];
            float2 t0, t1;
            t0.x = acc[mf][nf][0] + b0; t0.y = acc[mf][nf][1] + b1;
            t1.x = acc[mf][nf][2] + b0; t1.y = acc[mf][nf][3] + b1;
            *(float2*)(out + (size_t)ra*EE + gc) = t0;
            *(float2*)(out + (size_t)rb*EE + gc) = t1;
        }
    }
}

// ---------------- launch ----------------
extern "C" void kernel_launch(void* const* d_in, const int* in_sizes, int n_in,
                              void* d_out, int out_size) {
    const float* x  = (const float*)d_in[0];
    const float* Wq = (const float*)d_in[1];
    const float* Bq = (const float*)d_in[2];
    const float* Wk = (const float*)d_in[3];
    const float* Bk = (const float*)d_in[4];
    const float* Wv = (const float*)d_in[5];
    const float* Bv = (const float*)d_in[6];
    const float* Pw = (const float*)d_in[7];
    const float* Pb = (const float*)d_in[8];
    float* out = (float*)d_out;

    qkv_kernel<<<1024, 256>>>(x, Wq, Bq, Wk, Bk, Wv, Bv);
    attn_kernel<<<dim3(32, 32), 128>>>();
    proj_kernel<<<dim3(8, 32), 256>>>(Pw, Pb, out);
}

// round 11
// speedup vs baseline: 5.0903x; 1.7947x over previous
#include <cuda_runtime.h>

#define BB 2
#define SS 2048
#define EE 1024
#define HH 16
#define DD 64

typedef unsigned long long u64;
typedef unsigned int u32;

__device__ __forceinline__ u32 cvt_tf32(float f) {
    u32 u; asm("cvt.rna.tf32.f32 %0, %1;" : "=r"(u) : "f"(f)); return u;
}
__device__ __forceinline__ void mma_tf32(float* c, const u32* a, u32 b0, u32 b1) {
    asm("mma.sync.aligned.m16n8k8.row.col.f32.tf32.tf32.f32 "
        "{%0,%1,%2,%3}, {%4,%5,%6,%7}, {%8,%9}, {%0,%1,%2,%3};"
        : "+f"(c[0]), "+f"(c[1]), "+f"(c[2]), "+f"(c[3])
        : "r"(a[0]), "r"(a[1]), "r"(a[2]), "r"(a[3]), "r"(b0), "r"(b1));
}
__device__ __forceinline__ void cp_async16(void* smem, const void* gptr) {
    u32 sa = (u32)__cvta_generic_to_shared(smem);
    asm volatile("cp.async.cg.shared.global [%0], [%1], 16;" :: "r"(sa), "l"(gptr));
}
__device__ __forceinline__ void cp_commit() { asm volatile("cp.async.commit_group;"); }
template<int N> __device__ __forceinline__ void cp_wait() {
    asm volatile("cp.async.wait_group %0;" :: "n"(N));
}

// ---------------- scratch ----------------
__device__ float g_q[BB*HH*SS*DD];     // [b,h,s,d]
__device__ float g_k[BB*HH*SS*DD];
__device__ float g_v[BB*HH*SS*DD];
__device__ float g_attn[BB*SS*EE];     // [b,s,h*d]

// ---------------- QKV projection via tf32 mma, x split hi+lo (R7, 65us) ----------------
#define QSTR 36
__global__ __launch_bounds__(256) void qkv_kernel(
    const float* __restrict__ x,
    const float* __restrict__ Wq, const float* __restrict__ Bq,
    const float* __restrict__ Wk, const float* __restrict__ Bk,
    const float* __restrict__ Wv, const float* __restrict__ Bv)
{
    __shared__ u32 Ah[64*QSTR];
    __shared__ u32 Al[64*QSTR];
    __shared__ u32 Wsm[192*QSTR];

    int tid  = threadIdx.x;
    int warp = tid >> 5;
    int lane = tid & 31;
    int g    = lane >> 2;
    int tg   = lane & 3;
    int wm0  = (warp >> 2) * 32;
    int wn0  = (warp & 3) * 48;
    int r0   = blockIdx.x * 64;

    const float* Ws[3] = {Wq, Wk, Wv};

    float acc[2][6][4];
    #pragma unroll
    for (int mf = 0; mf < 2; ++mf)
        #pragma unroll
        for (int nf = 0; nf < 6; ++nf)
            #pragma unroll
            for (int j = 0; j < 4; ++j) acc[mf][nf][j] = 0.f;

    for (int k0 = 0; k0 < 64; k0 += 32) {
        if (k0) __syncthreads();
        #pragma unroll
        for (int it = 0; it < 2; ++it) {
            int idx = it*256 + tid;
            int row = idx >> 3;
            int c4  = (idx & 7) * 4;
            float4 v = *(const float4*)(x + (size_t)(r0+row)*64 + k0 + c4);
            uint4 h, l;
            h.x = cvt_tf32(v.x); l.x = cvt_tf32(v.x - __uint_as_float(h.x));
            h.y = cvt_tf32(v.y); l.y = cvt_tf32(v.y - __uint_as_float(h.y));
            h.z = cvt_tf32(v.z); l.z = cvt_tf32(v.z - __uint_as_float(h.z));
            h.w = cvt_tf32(v.w); l.w = cvt_tf32(v.w - __uint_as_float(h.w));
            *(uint4*)&Ah[row*QSTR + c4] = h;
            *(uint4*)&Al[row*QSTR + c4] = l;
        }
        #pragma unroll
        for (int it = 0; it < 6; ++it) {
            int idx = it*256 + tid;
            int row = idx >> 3;
            int c4  = (idx & 7) * 4;
            float4 v = *(const float4*)(Ws[row >> 6] + (size_t)(row & 63)*64 + k0 + c4);
            uint4 h;
            h.x = cvt_tf32(v.x); h.y = cvt_tf32(v.y);
            h.z = cvt_tf32(v.z); h.w = cvt_tf32(v.w);
            *(uint4*)&Wsm[row*QSTR + c4] = h;
        }
        __syncthreads();

        #pragma unroll
        for (int ks = 0; ks < 4; ++ks) {
            int kk = ks * 8;
            u32 ah[2][4], al[2][4];
            #pragma unroll
            for (int mf = 0; mf < 2; ++mf) {
                int mr = wm0 + mf*16;
                ah[mf][0] = Ah[(mr+g)*QSTR   + kk + tg];
                ah[mf][1] = Ah[(mr+g+8)*QSTR + kk + tg];
                ah[mf][2] = Ah[(mr+g)*QSTR   + kk + tg + 4];
                ah[mf][3] = Ah[(mr+g+8)*QSTR + kk + tg + 4];
                al[mf][0] = Al[(mr+g)*QSTR   + kk + tg];
                al[mf][1] = Al[(mr+g+8)*QSTR + kk + tg];
                al[mf][2] = Al[(mr+g)*QSTR   + kk + tg + 4];
                al[mf][3] = Al[(mr+g+8)*QSTR + kk + tg + 4];
            }
            #pragma unroll
            for (int nf = 0; nf < 6; ++nf) {
                u32 b0 = Wsm[(wn0 + nf*8 + g)*QSTR + kk + tg];
                u32 b1 = Wsm[(wn0 + nf*8 + g)*QSTR + kk + tg + 4];
                #pragma unroll
                for (int mf = 0; mf < 2; ++mf) {
                    mma_tf32(acc[mf][nf], ah[mf], b0, b1);
                    mma_tf32(acc[mf][nf], al[mf], b0, b1);
                }
            }
        }
    }

    const float* Bias[3] = {Bq, Bk, Bv};
    float* Gs[3];
    Gs[0] = g_q; Gs[1] = g_k; Gs[2] = g_v;
    #pragma unroll
    for (int mf = 0; mf < 2; ++mf) {
        int ra = r0 + wm0 + mf*16 + g;
        int rb = ra + 8;
        #pragma unroll
        for (int nf = 0; nf < 6; ++nf) {
            int gc  = wn0 + nf*8 + 2*tg;
            int mat = gc >> 6;
            int c   = gc & 63;
            float b0 = Bias[mat][c], b1 = Bias[mat][c+1];
            {
                int h = ra & 15, bs = ra >> 4, s = bs & 2047, b = bs >> 11;
                float2 t; t.x = acc[mf][nf][0] + b0; t.y = acc[mf][nf][1] + b1;
                *(float2*)(Gs[mat] + ((size_t)((b*HH + h)*SS) + s)*DD + c) = t;
            }
            {
                int h = rb & 15, bs = rb >> 4, s = bs & 2047, b = bs >> 11;
                float2 t; t.x = acc[mf][nf][2] + b0; t.y = acc[mf][nf][3] + b1;
                *(float2*)(Gs[mat] + ((size_t)((b*HH + h)*SS) + s)*DD + c) = t;
            }
        }
    }
}

// ---------------- flash attention: tf32 mma + cp.async pipelined K/V ----------------
#define KSTR 68
#define ATTN_SMEM (2*64*KSTR*4 + 2*64*64*4)   // Kt/Vt tf32 + raw staging = 67584 B

__device__ __forceinline__ void attn_issue_tile(
    const float* Kb, const float* Vb, float* stK, float* stV, int k0, int tid)
{
    #pragma unroll
    for (int u = 0; u < 8; ++u) {
        int lin = u*128 + tid;
        int key = lin >> 4;
        int d4  = (lin & 15) * 4;
        cp_async16(stK + key*64 + d4, Kb + (size_t)(k0+key)*64 + d4);
        cp_async16(stV + key*64 + d4, Vb + (size_t)(k0+key)*64 + d4);
    }
}

__global__ __launch_bounds__(128) void attn_kernel()
{
    extern __shared__ u32 dsm[];
    u32* Kt = dsm;
    u32* Vt = dsm + 64*KSTR;
    float* stK = (float*)(dsm + 2*64*KSTR);
    float* stV = stK + 64*64;

    int tid  = threadIdx.x;
    int warp = tid >> 5;
    int lane = tid & 31;
    int g    = lane >> 2;
    int tg   = lane & 3;

    int bh = blockIdx.y;
    int qt = 31 - (int)blockIdx.x;
    int q0 = qt * 64;

    const float* Qb = g_q + (size_t)bh*SS*DD;
    const float* Kb = g_k + (size_t)bh*SS*DD;
    const float* Vb = g_v + (size_t)bh*SS*DD;

    int r0 = q0 + warp*16 + g;
    int r1 = r0 + 8;

    // prefetch tile 0
    attn_issue_tile(Kb, Vb, stK, stV, 0, tid);
    cp_commit();

    u32 qa[8][4];
    #pragma unroll
    for (int k = 0; k < 8; ++k) {
        qa[k][0] = cvt_tf32(Qb[(size_t)r0*64 + k*8 + tg]     * 0.125f);
        qa[k][1] = cvt_tf32(Qb[(size_t)r1*64 + k*8 + tg]     * 0.125f);
        qa[k][2] = cvt_tf32(Qb[(size_t)r0*64 + k*8 + tg + 4] * 0.125f);
        qa[k][3] = cvt_tf32(Qb[(size_t)r1*64 + k*8 + tg + 4] * 0.125f);
    }

    float accO[8][4];
    #pragma unroll
    for (int n = 0; n < 8; ++n)
        #pragma unroll
        for (int j = 0; j < 4; ++j) accO[n][j] = 0.f;
    float m0 = -3.0e38f, m1 = -3.0e38f, l0 = 0.f, l1 = 0.f;

    for (int t = 0; t <= qt; ++t) {
        int k0 = t * 64;
        cp_wait<0>();
        __syncthreads();                 // staging ready; Kt/Vt free (prev compute done)

        // producer: raw fp32 -> tf32 operands (identical rounding to R7)
        #pragma unroll
        for (int u = 0; u < 8; ++u) {
            int lin = u*128 + tid;
            int key = lin >> 4;
            int d4  = (lin & 15) * 4;
            float4 kv = *(const float4*)(stK + key*64 + d4);
            float4 vv = *(const float4*)(stV + key*64 + d4);
            uint4 ku, vu;
            ku.x = cvt_tf32(kv.x); ku.y = cvt_tf32(kv.y); ku.z = cvt_tf32(kv.z); ku.w = cvt_tf32(kv.w);
            vu.x = cvt_tf32(vv.x); vu.y = cvt_tf32(vv.y); vu.z = cvt_tf32(vv.z); vu.w = cvt_tf32(vv.w);
            *(uint4*)&Kt[key*KSTR + d4] = ku;
            *(uint4*)&Vt[key*KSTR + d4] = vu;
        }
        __syncthreads();                 // operands ready; staging free

        if (t < qt) attn_issue_tile(Kb, Vb, stK, stV, k0 + 64, tid);
        cp_commit();                     // (empty group on last tile)

        // S = Q K^T
        float sfr[8][4];
        #pragma unroll
        for (int n = 0; n < 8; ++n) {
            float c[4] = {0.f, 0.f, 0.f, 0.f};
            #pragma unroll
            for (int k = 0; k < 8; ++k) {
                u32 b0 = Kt[(n*8 + g)*KSTR + k*8 + tg];
                u32 b1 = Kt[(n*8 + g)*KSTR + k*8 + tg + 4];
                mma_tf32(c, qa[k], b0, b1);
            }
            sfr[n][0] = c[0]; sfr[n][1] = c[1]; sfr[n][2] = c[2]; sfr[n][3] = c[3];
        }

        if (t == qt) {
            #pragma unroll
            for (int n = 0; n < 8; ++n) {
                int col = k0 + n*8 + 2*tg;
                if (col     > r0) sfr[n][0] = -1e30f;
                if (col + 1 > r0) sfr[n][1] = -1e30f;
                if (col     > r1) sfr[n][2] = -1e30f;
                if (col + 1 > r1) sfr[n][3] = -1e30f;
            }
        }

        float mx0 = -3.0e38f, mx1 = -3.0e38f;
        #pragma unroll
        for (int n = 0; n < 8; ++n) {
            mx0 = fmaxf(mx0, fmaxf(sfr[n][0], sfr[n][1]));
            mx1 = fmaxf(mx1, fmaxf(sfr[n][2], sfr[n][3]));
        }
        mx0 = fmaxf(mx0, __shfl_xor_sync(0xffffffffu, mx0, 1));
        mx0 = fmaxf(mx0, __shfl_xor_sync(0xffffffffu, mx0, 2));
        mx1 = fmaxf(mx1, __shfl_xor_sync(0xffffffffu, mx1, 1));
        mx1 = fmaxf(mx1, __shfl_xor_sync(0xffffffffu, mx1, 2));
        float nm0 = fmaxf(m0, mx0), nm1 = fmaxf(m1, mx1);
        float cr0 = __expf(m0 - nm0), cr1 = __expf(m1 - nm1);
        m0 = nm0; m1 = nm1;
        l0 *= cr0; l1 *= cr1;
        #pragma unroll
        for (int n = 0; n < 8; ++n) {
            accO[n][0] *= cr0; accO[n][1] *= cr0;
            accO[n][2] *= cr1; accO[n][3] *= cr1;
        }
        float p[8][4];
        float ps0 = 0.f, ps1 = 0.f;
        #pragma unroll
        for (int n = 0; n < 8; ++n) {
            p[n][0] = __expf(sfr[n][0] - nm0);
            p[n][1] = __expf(sfr[n][1] - nm0);
            p[n][2] = __expf(sfr[n][2] - nm1);
            p[n][3] = __expf(sfr[n][3] - nm1);
            ps0 += p[n][0] + p[n][1];
            ps1 += p[n][2] + p[n][3];
        }
        l0 += ps0; l1 += ps1;

        __syncthreads();                 // all warps done reading Kt (QK)
        u32* Pw = Kt + warp*16*KSTR;     // P aliases Kt, per-warp region
        #pragma unroll
        for (int n = 0; n < 8; ++n) {
            Pw[g*KSTR       + n*8 + 2*tg]     = cvt_tf32(p[n][0]);
            Pw[g*KSTR       + n*8 + 2*tg + 1] = cvt_tf32(p[n][1]);
            Pw[(g+8)*KSTR   + n*8 + 2*tg]     = cvt_tf32(p[n][2]);
            Pw[(g+8)*KSTR   + n*8 + 2*tg + 1] = cvt_tf32(p[n][3]);
        }
        __syncwarp();

        #pragma unroll
        for (int k2 = 0; k2 < 8; ++k2) {
            u32 a[4];
            a[0] = Pw[g*KSTR     + k2*8 + tg];
            a[1] = Pw[(g+8)*KSTR + k2*8 + tg];
            a[2] = Pw[g*KSTR     + k2*8 + tg + 4];
            a[3] = Pw[(g+8)*KSTR + k2*8 + tg + 4];
            #pragma unroll
            for (int n2 = 0; n2 < 8; ++n2) {
                u32 b0 = Vt[(k2*8 + tg)*KSTR     + n2*8 + g];
                u32 b1 = Vt[(k2*8 + tg + 4)*KSTR + n2*8 + g];
                mma_tf32(accO[n2], a, b0, b1);
            }
        }
    }

    l0 += __shfl_xor_sync(0xffffffffu, l0, 1);
    l0 += __shfl_xor_sync(0xffffffffu, l0, 2);
    l1 += __shfl_xor_sync(0xffffffffu, l1, 1);
    l1 += __shfl_xor_sync(0xffffffffu, l1, 2);
    float inv0 = 1.f / l0, inv1 = 1.f / l1;

    int b = bh >> 4, h = bh & (HH-1);
    float* out0 = g_attn + ((size_t)(b*SS + r0))*EE + h*DD;
    float* out1 = g_attn + ((size_t)(b*SS + r1))*EE + h*DD;
    #pragma unroll
    for (int n2 = 0; n2 < 8; ++n2) {
        float2 v0, v1;
        v0.x = accO[n2][0]*inv0; v0.y = accO[n2][1]*inv0;
        v1.x = accO[n2][2]*inv1; v1.y = accO[n2][3]*inv1;
        *(float2*)(out0 + n2*8 + 2*tg) = v0;
        *(float2*)(out1 + n2*8 + 2*tg) = v1;
    }
}

// ---------------- output projection: tf32 mma + cp.async 2-stage, BK=32 ----------------
#define PK 32
#define PSTR2 36
#define PROJ_SMEM (2*128*PSTR2*4 + 2*2*128*PK*4)   // operands 36864 + staging 65536 = 102400 B

__device__ __forceinline__ void proj_issue(
    const float* __restrict__ W, float* stA, float* stB,
    int m0, int n0, int i, int tid)
{
    if (i < EE/PK) {
        int k0 = i * PK;
        float* sA = stA + (i & 1) * 128*PK;
        float* sB = stB + (i & 1) * 128*PK;
        #pragma unroll
        for (int it = 0; it < 4; ++it) {
            int idx = it*256 + tid;
            int row = idx >> 3;
            int c4  = (idx & 7) * 4;
            cp_async16(sA + row*PK + c4, g_attn + (size_t)(m0+row)*EE + k0 + c4);
            cp_async16(sB + row*PK + c4, W + (size_t)(n0+row)*EE + k0 + c4);
        }
    }
    cp_commit();
}

__global__ __launch_bounds__(256) void proj_kernel(
    const float* __restrict__ W, const float* __restrict__ bias, float* __restrict__ out)
{
    extern __shared__ u32 dsm[];
    u32* As = dsm;                       // [128][36] tf32
    u32* Bs = dsm + 128*PSTR2;
    float* stA = (float*)(dsm + 2*128*PSTR2);
    float* stB = stA + 2*128*PK;

    int tid  = threadIdx.x;
    int warp = tid >> 5;
    int lane = tid & 31;
    int g    = lane >> 2;
    int tg   = lane & 3;
    int wm0  = (warp >> 1) * 32;
    int wn0  = (warp & 1) * 64;
    int m0   = blockIdx.y * 128;
    int n0   = blockIdx.x * 128;

    float acc[2][8][4];
    #pragma unroll
    for (int mf = 0; mf < 2; ++mf)
        #pragma unroll
        for (int nf = 0; nf < 8; ++nf)
            #pragma unroll
            for (int j = 0; j < 4; ++j) acc[mf][nf][j] = 0.f;

    proj_issue(W, stA, stB, m0, n0, 0, tid);
    proj_issue(W, stA, stB, m0, n0, 1, tid);

    for (int i = 0; i < EE/PK; ++i) {
        cp_wait<1>();
        __syncthreads();                 // stage[i&1] ready; prev compute done

        float* sA = stA + (i & 1) * 128*PK;
        float* sB = stB + (i & 1) * 128*PK;
        #pragma unroll
        for (int it = 0; it < 4; ++it) {
            int idx = it*256 + tid;
            int row = idx >> 3;
            int c4  = (idx & 7) * 4;
            float4 a = *(const float4*)(sA + row*PK + c4);
            uint4 ha;
            ha.x = cvt_tf32(a.x); ha.y = cvt_tf32(a.y); ha.z = cvt_tf32(a.z); ha.w = cvt_tf32(a.w);
            *(uint4*)&As[row*PSTR2 + c4] = ha;
            float4 b = *(const float4*)(sB + row*PK + c4);
            uint4 hb;
            hb.x = cvt_tf32(b.x); hb.y = cvt_tf32(b.y); hb.z = cvt_tf32(b.z); hb.w = cvt_tf32(b.w);
            *(uint4*)&Bs[row*PSTR2 + c4] = hb;
        }
        __syncthreads();                 // operands ready; stage slot free

        proj_issue(W, stA, stB, m0, n0, i + 2, tid);

        #pragma unroll
        for (int ks = 0; ks < 4; ++ks) {
            int kk = ks * 8;
            u32 a[2][4];
            #pragma unroll
            for (int mf = 0; mf < 2; ++mf) {
                int mr = wm0 + mf*16;
                a[mf][0] = As[(mr+g)*PSTR2   + kk + tg];
                a[mf][1] = As[(mr+g+8)*PSTR2 + kk + tg];
                a[mf][2] = As[(mr+g)*PSTR2   + kk + tg + 4];
                a[mf][3] = As[(mr+g+8)*PSTR2 + kk + tg + 4];
            }
            #pragma unroll
            for (int nf = 0; nf < 8; ++nf) {
                u32 b0 = Bs[(wn0 + nf*8 + g)*PSTR2 + kk + tg];
                u32 b1 = Bs[(wn0 + nf*8 + g)*PSTR2 + kk + tg + 4];
                #pragma unroll
                for (int mf = 0; mf < 2; ++mf)
                    mma_tf32(acc[mf][nf], a[mf], b0, b1);
            }
        }
    }

    #pragma unroll
    for (int mf = 0; mf < 2; ++mf) {
        int ra = m0 + wm0 + mf*16 + g;
        int rb = ra + 8;
        #pragma unroll
        for (int nf = 0; nf < 8; ++nf) {
            int gc = n0 + wn0 + nf*8 + 2*tg;
            float b0 = bias[gc], b1 = bias[gc+1];
            float2 t0, t1;
            t0.x = acc[mf][nf][0] + b0; t0.y = acc[mf][nf][1] + b1;
            t1.x = acc[mf][nf][2] + b0; t1.y = acc[mf][nf][3] + b1;
            *(float2*)(out + (size_t)ra*EE + gc) = t0;
            *(float2*)(out + (size_t)rb*EE + gc) = t1;
        }
    }
}

// ---------------- launch ----------------
extern "C" void kernel_launch(void* const* d_in, const int* in_sizes, int n_in,
                              void* d_out, int out_size) {
    const float* x  = (const float*)d_in[0];
    const float* Wq = (const float*)d_in[1];
    const float* Bq = (const float*)d_in[2];
    const float* Wk = (const float*)d_in[3];
    const float* Bk = (const float*)d_in[4];
    const float* Wv = (const float*)d_in[5];
    const float* Bv = (const float*)d_in[6];
    const float* Pw = (const float*)d_in[7];
    const float* Pb = (const float*)d_in[8];
    float* out = (float*)d_out;

    cudaFuncSetAttribute(attn_kernel, cudaFuncAttributeMaxDynamicSharedMemorySize, ATTN_SMEM);
    cudaFuncSetAttribute(proj_kernel, cudaFuncAttributeMaxDynamicSharedMemorySize, PROJ_SMEM);

    qkv_kernel<<<1024, 256>>>(x, Wq, Bq, Wk, Bk, Wv, Bv);
    attn_kernel<<<dim3(32, 32), 128, ATTN_SMEM>>>();
    proj_kernel<<<dim3(8, 32), 256, PROJ_SMEM>>>(Pw, Pb, out);
}